// round 13
// baseline (speedup 1.0000x reference)
#include <cuda_runtime.h>
#include <cstdint>

// ---------------------------------------------------------------------------
// VectorBasis: out[a,m,o] = sum_{edges e with center a}
//     fc(d_e) * Y_m(e) * sum_n R_n(d_e) * T[sc_a, sn_e, n, o]
// where T[sc,sn,n,o] = sum_q W_alch[sn,q] * emb[sc, n*4+q] * Wc[o, n*4+q]
//
// R13: TWO launches. The species->u8 pack is fused into the edge kernel:
//   blocks bid < pack_blocks pack a spec8 slice (prologue), release-add a
//   global counter; all blocks build sT + load their edge data first, then
//   acquire-spin on the counter before gathering spec8. finalize resets the
//   counter (and zeroes scratch) to restore per-call invariants.
// Deadlock-safe: packer blocks are the lowest bids -> all in wave 1
// (edge runs ~6 blocks/SM -> wave 1 ~888 blocks >> 98 packers).
// Scratch layout: padded m-rows scratch[a*12 + m*4 + o], lane 3 = pad.
// g_scratch / g_pack_done zero at module load; finalize restores both.
// ---------------------------------------------------------------------------

#define A_MAX 100000
__device__ float         g_scratch[A_MAX * 12];
__device__ unsigned char g_spec8[A_MAX + 4];
__device__ unsigned int  g_pack_done;   // 0 at load; reset by finalize

__device__ __forceinline__ void red_add_v4(float* p, float a, float b, float c, float d) {
    asm volatile("red.global.add.v4.f32 [%0], {%1, %2, %3, %4};"
                 :: "l"(p), "f"(a), "f"(b), "f"(c), "f"(d)
                 : "memory");
}
__device__ __forceinline__ void red_release_add(unsigned int* p, unsigned int v) {
    asm volatile("red.release.gpu.global.add.u32 [%0], %1;"
                 :: "l"(p), "r"(v) : "memory");
}
__device__ __forceinline__ unsigned int ld_acquire(const unsigned int* p) {
    unsigned int v;
    asm volatile("ld.acquire.gpu.global.u32 %0, [%1];" : "=r"(v) : "l"(p) : "memory");
    return v;
}

#define EPB 1024   // edges per block (256 threads x 4)

__device__ __forceinline__ void process_edge(
    float vx, float vy, float vz, int a, int nb,
    const unsigned char* __restrict__ spec8,
    const float* __restrict__ sT,
    float* __restrict__ scratch)
{
    float d2   = fmaf(vx, vx, fmaf(vy, vy, vz * vz)) + 1e-12f;
    float invd = rsqrtf(d2);
    float d    = d2 * invd;

    int sc = (int)__ldg(&spec8[a]);
    int sn = (int)__ldg(&spec8[nb]);
    const float* T = &sT[(sc * 4 + sn) * 25];

    // R_n = sin(n*pi*d/rc)/d via scalar Chebyshev recurrence
    float s, c;
    __sincosf(0.62831853071795864769f * d, &s, &c);  // pi/5 * d
    float twoc = 2.0f * c;
    float r_nm1 = 0.0f;
    float r_n   = s * invd;

    float h0 = 0.f, h1 = 0.f, h2 = 0.f;
#pragma unroll
    for (int n = 0; n < 8; n++) {
        h0 = fmaf(r_n, T[n * 3 + 0], h0);
        h1 = fmaf(r_n, T[n * 3 + 1], h1);
        h2 = fmaf(r_n, T[n * 3 + 2], h2);
        float r_np1 = fmaf(twoc, r_n, -r_nm1);
        r_nm1 = r_n;
        r_n   = r_np1;
    }

    // shifted-cosine cutoff (rc=5, width=0.5)
    float fc;
    if (d < 4.5f) {
        fc = 1.0f;
    } else if (d < 5.0f) {
        fc = 0.5f * (__cosf(6.28318530717958647692f * (d - 4.5f)) + 1.0f);
    } else {
        fc = 0.0f;
    }

    float f  = fc * invd;
    float y0 = vy * f;   // m order (-1,0,1) -> (y,z,x)/d
    float y1 = vz * f;
    float y2 = vx * f;

    // padded m-row layout: rows m at +0,+4,+8; lane 3 = pad
    float* base = scratch + (size_t)a * 12;
    red_add_v4(base + 0, y0 * h0, y0 * h1, y0 * h2, 0.0f);
    red_add_v4(base + 4, y1 * h0, y1 * h1, y1 * h2, 0.0f);
    red_add_v4(base + 8, y2 * h0, y2 * h1, y2 * h2, 0.0f);
}

__global__ void __launch_bounds__(256)
edge_kernel(const float* __restrict__ vecs,     // (E,3)
            const int*   __restrict__ centers,  // (E,)
            const int*   __restrict__ neighbors,// (E,)
            const int*   __restrict__ species,  // (A,) int32 source
            const float* __restrict__ W_alch,   // (4,4)
            const float* __restrict__ emb,      // (4,32)
            const float* __restrict__ Wc,       // (3,32)
            float*       __restrict__ scratch,  // (A,12)
            unsigned char* __restrict__ spec8,  // (A,) packed (written+read here)
            int E, int A, int pack_blocks)
{
    // ---- fused species pack (blocks [0, pack_blocks)) ----
    if ((int)blockIdx.x < pack_blocks) {
        int i = blockIdx.x * 256 + threadIdx.x;
        int np = A >> 2;
        if (i < np) {
            int4 sp = ((const int4*)species)[i];
            ((uchar4*)spec8)[i] = make_uchar4((unsigned char)sp.x, (unsigned char)sp.y,
                                              (unsigned char)sp.z, (unsigned char)sp.w);
        }
        if (i == np) {
            for (int j = np * 4; j < A; j++) spec8[j] = (unsigned char)species[j];
        }
        __threadfence();
        __syncthreads();
        if (threadIdx.x == 0) red_release_add(&g_pack_done, 1u);
    }

    // ---- independent preamble: sT table (stride 25, conflict-free) ----
    __shared__ float sT[16 * 25];
    {
        int t = threadIdx.x;
        if (t < 192) {
            int idx0 = t * 2;
#pragma unroll
            for (int u = 0; u < 2; u++) {
                int idx = idx0 + u;            // 0..383 = 16*24
                int p = idx / 24, r = idx - p * 24;
                int n = r / 3,  o = r - n * 3;
                int sc = p >> 2, sn = p & 3;
                float v = 0.f;
#pragma unroll
                for (int q = 0; q < 4; q++) {
                    int dd = n * 4 + q;
                    v = fmaf(W_alch[sn * 4 + q] * emb[sc * 32 + dd], Wc[o * 32 + dd], v);
                }
                sT[p * 25 + r] = v;
            }
        }
    }

    int e0 = blockIdx.x * EPB;
    int t  = threadIdx.x;
    int base = e0 + t * 4;
    bool full = (e0 + EPB <= E);

    // ---- load edge data (independent of spec8) ----
    float4 va, vb, vc;
    int4 cc, nn;
    if (full) {
        const float4* v4 = (const float4*)(vecs + (size_t)e0 * 3);
        va = v4[t * 3 + 0];
        vb = v4[t * 3 + 1];
        vc = v4[t * 3 + 2];
        cc = *(const int4*)(centers   + base);
        nn = *(const int4*)(neighbors + base);
    }

    // ---- wait for pack completion ----
    if (threadIdx.x == 0) {
        while (ld_acquire(&g_pack_done) < (unsigned)pack_blocks) __nanosleep(64);
    }
    __syncthreads();   // also covers the sT build

    if (full) {
        process_edge(va.x, va.y, va.z, cc.x, nn.x, spec8, sT, scratch);
        process_edge(va.w, vb.x, vb.y, cc.y, nn.y, spec8, sT, scratch);
        process_edge(vb.z, vb.w, vc.x, cc.z, nn.z, spec8, sT, scratch);
        process_edge(vc.y, vc.z, vc.w, cc.w, nn.w, spec8, sT, scratch);
    } else {
#pragma unroll
        for (int j = 0; j < 4; j++) {
            int e = base + j;
            if (e < E) {
                float vx = vecs[(size_t)e * 3 + 0];
                float vy = vecs[(size_t)e * 3 + 1];
                float vz = vecs[(size_t)e * 3 + 2];
                process_edge(vx, vy, vz, centers[e], neighbors[e], spec8, sT, scratch);
            }
        }
    }
}

// Flat finalize + zero-writeback: thread i owns scratch float4-row i
// (atom a = i/3, row m = i%3). Also resets the pack counter.
__global__ void __launch_bounds__(256)
finalize_kernel(float4* __restrict__ scratch4, float* __restrict__ out, int nrows)
{
    int i = blockIdx.x * blockDim.x + threadIdx.x;
    if (i == 0) g_pack_done = 0;           // restore per-call invariant
    if (i >= nrows) return;
    float4 v = scratch4[i];
    int a = i / 3;
    int m = i - a * 3;
    float* o = out + (size_t)a * 9 + m * 3;
    o[0] = v.x;
    o[1] = v.y;
    o[2] = v.z;
    scratch4[i] = make_float4(0.f, 0.f, 0.f, 0.f);
}

extern "C" void kernel_launch(void* const* d_in, const int* in_sizes, int n_in,
                              void* d_out, int out_size)
{
    const float* vecs      = (const float*)d_in[0];
    const int*   centers   = (const int*)  d_in[1];
    const int*   neighbors = (const int*)  d_in[2];
    const int*   species   = (const int*)  d_in[3];
    // d_in[4], d_in[5] unused by reference
    const float* W_alch    = (const float*)d_in[6];
    const float* emb       = (const float*)d_in[7];
    const float* Wc        = (const float*)d_in[8];

    int E = in_sizes[1];
    int A = in_sizes[3];

    float* scratch = nullptr;
    cudaGetSymbolAddress((void**)&scratch, g_scratch);
    unsigned char* spec8 = nullptr;
    cudaGetSymbolAddress((void**)&spec8, g_spec8);

    int eblocks = (E + EPB - 1) / EPB;
    int pack_threads = (A >> 2) + 1;
    int pack_blocks  = (pack_threads + 255) / 256;
    if (pack_blocks > eblocks) pack_blocks = eblocks;  // safety (not hit: 98 << 1563)

    edge_kernel<<<eblocks, 256>>>(vecs, centers, neighbors, species,
                                  W_alch, emb, Wc, scratch, spec8,
                                  E, A, pack_blocks);

    int nrows = A * 3;
    finalize_kernel<<<(nrows + 255) / 256, 256>>>((float4*)scratch, (float*)d_out, nrows);
}